// round 17
// baseline (speedup 1.0000x reference)
#include <cuda_runtime.h>
#include <cuda_fp16.h>
#include <cstdint>

#define B_TOTAL  8192
#define T_STEPS  512
#define HID      128
#define BM       16      // rows per CTA (one 16-row M-tile, shared by 2 warps)
#define NTHREADS 64      // 2 warps: n-split (warp0: nt 0-7, warp1: nt 8-15)
#define NKT      9       // k-tiles: 128 h + [x0,x1,bias,0..] tile
#define NNT      16      // n-tiles total
#define ALPHA_C  0.2f
#define BETA_C   0.7f

// B fragments (f16): one uint4 per (ntp,kt,lane) covering TWO n-tiles
#define SB_BYTES  (8 * NKT * 32 * 16)        // 36864
#define SWP_OFF   SB_BYTES                   // 512 B (padded to 1024)
#define SX_OFF    (SB_BYTES + 1024)          // fragment exchange: 2buf x 2wid x 4g x 32l x 16B
#define SX_BYTES  (2 * 2 * 4 * 32 * 16)      // 8192
#define SRED_OFF  (SX_OFF + SX_BYTES)        // 16 floats
#define SMEM_TOT  (SRED_OFF + 64)

__device__ __forceinline__ float tanh_hw(float x) {
    float y; asm("tanh.approx.f32 %0, %1;" : "=f"(y) : "f"(x)); return y;
}
__device__ __forceinline__ uint32_t f16x2(float lo, float hi) {
    uint32_t r; asm("cvt.rn.f16x2.f32 %0, %1, %2;" : "=r"(r) : "f"(hi), "f"(lo));
    return r;
}
__device__ __forceinline__ void mma16816(float c[4], const uint32_t a[4],
                                         uint32_t b0, uint32_t b1) {
    asm("mma.sync.aligned.m16n8k16.row.col.f32.f16.f16.f32 "
        "{%0,%1,%2,%3}, {%4,%5,%6,%7}, {%8,%9}, {%0,%1,%2,%3};"
        : "+f"(c[0]), "+f"(c[1]), "+f"(c[2]), "+f"(c[3])
        : "r"(a[0]), "r"(a[1]), "r"(a[2]), "r"(a[3]), "r"(b0), "r"(b1));
}

extern __shared__ char smem[];

__global__ __launch_bounds__(NTHREADS, 4)
void rnn_kernel(const float* __restrict__ input,   // (B, T, 2)
                const float* __restrict__ W_rec,   // (130, 128)
                const float* __restrict__ b_rec,   // (128)
                const float* __restrict__ W_out,   // (128, 1)
                const float* __restrict__ b_out,   // (1)
                float* __restrict__ out)           // (B)
{
    uint4*  sB  = (uint4*)smem;                    // [ntp][kt][lane]
    float2* sWP = (float2*)(smem + SWP_OFF);       // [nt][tig] wout col pairs
    uint4*  sX  = (uint4*)(smem + SX_OFF);         // fragment exchange
    float*  sRed = (float*)(smem + SRED_OFF);

    const int tid  = threadIdx.x;
    const int lane = tid & 31;
    const int wid  = tid >> 5;      // 0 or 1
    const int tig  = lane & 3;      // col group within fragment
    const int gid  = lane >> 2;     // row group 0..7
    const int bBase = blockIdx.x * BM;

    const int ntpB  = wid * 4;      // own B fragment pairs
    const int ntB   = wid * 8;      // own n-tiles
    const int ktOwn = wid * 4;      // own produced k-tile fragments
    const int ktOth = (wid ^ 1) * 4;

    // ---- build B fragments: W'(k,n) rounded to f16
    // W'(k,n): k<128 -> W_rec[k+2][n]; 128->W_rec[0][n]; 129->W_rec[1][n];
    //          130 -> b_rec[n]; else 0.
    for (int idx = tid; idx < 8 * NKT * 32; idx += NTHREADS) {
        int l   = idx & 31;
        int kt  = (idx >> 5) % NKT;
        int ntp = (idx >> 5) / NKT;
        int kb  = kt * 16 + 2 * (l & 3);
        unsigned short hq[2][4];
        #pragma unroll
        for (int half = 0; half < 2; half++) {
            int n = (2 * ntp + half) * 8 + (l >> 2);
            #pragma unroll
            for (int q = 0; q < 4; q++) {
                int k = kb + (q >> 1) * 8 + (q & 1);
                float v;
                if      (k < 128)  v = W_rec[(k + 2) * HID + n];
                else if (k == 128) v = W_rec[n];
                else if (k == 129) v = W_rec[HID + n];
                else if (k == 130) v = b_rec[n];
                else               v = 0.0f;
                hq[half][q] = __half_as_ushort(__float2half_rn(v));
            }
        }
        uint4 bv;
        bv.x = (uint32_t)hq[0][0] | ((uint32_t)hq[0][1] << 16);
        bv.y = (uint32_t)hq[0][2] | ((uint32_t)hq[0][3] << 16);
        bv.z = (uint32_t)hq[1][0] | ((uint32_t)hq[1][1] << 16);
        bv.w = (uint32_t)hq[1][2] | ((uint32_t)hq[1][3] << 16);
        sB[(ntp * NKT + kt) * 32 + l] = bv;
    }
    for (int i = tid; i < NNT * 4; i += NTHREADS) {
        int nt = i >> 2, c = i & 3;
        sWP[i] = make_float2(W_out[nt * 8 + 2 * c], W_out[nt * 8 + 2 * c + 1]);
    }
    __syncthreads();

    // ---- per-thread recurrent state (rows shared by both warps) ----
    const int r0 = gid;            // local rows r0 and r0+8
    const int r8 = gid + 8;
    const long long off0 = (long long)(bBase + r0) * (T_STEPS * 2);
    const long long off8 = (long long)(bBase + r8) * (T_STEPS * 2);
    const float bout = b_out[0];

    float2 x0c = *(const float2*)(input + off0);   // x_0
    float2 x8c = *(const float2*)(input + off8);
    float racc0 = 0.f, racc8 = 0.f, prev0 = 0.f, prev8 = 0.f;
    float oacc0 = 0.f, oacc8 = 0.f;

    const uint32_t ONEH = 0x00003C00u;   // {lo=1.0h (bias slot), hi=0}

    uint32_t a[NKT][4];
    #pragma unroll
    for (int kt = 0; kt < 8; kt++)
        #pragma unroll
        for (int q = 0; q < 4; q++) a[kt][q] = 0u;   // h_{-1} = 0
    a[8][0] = (tig == 0) ? f16x2(x0c.x, x0c.y) : (tig == 1) ? ONEH : 0u;
    a[8][1] = (tig == 0) ? f16x2(x8c.x, x8c.y) : (tig == 1) ? ONEH : 0u;
    a[8][2] = 0u; a[8][3] = 0u;

    for (int t = 0; t < T_STEPS; ++t) {
        float2 x0n = make_float2(0.f, 0.f), x8n = make_float2(0.f, 0.f);
        if (t + 1 < T_STEPS) {
            x0n = *(const float2*)(input + off0 + (long long)(t + 1) * 2);
            x8n = *(const float2*)(input + off8 + (long long)(t + 1) * 2);
        }

        // ---- GEMM: own n-half (8 n-tiles), all 9 k-tiles ----
        float c[8][4];
        #pragma unroll
        for (int p = 0; p < 8; p++) {
            c[p][0] = 0.f; c[p][1] = 0.f; c[p][2] = 0.f; c[p][3] = 0.f;
        }
        #pragma unroll
        for (int kt = 0; kt < NKT; kt++) {
            uint4 bv[4];
            #pragma unroll
            for (int p = 0; p < 4; p++)
                bv[p] = sB[((ntpB + p) * NKT + kt) * 32 + lane];
            #pragma unroll
            for (int p = 0; p < 4; p++) {
                mma16816(c[2 * p],     a[kt], bv[p].x, bv[p].y);
                mma16816(c[2 * p + 1], a[kt], bv[p].z, bv[p].w);
            }
        }

        // ---- epilogue: tanh own half -> omega partial -> own A fragments ----
        float pr0 = 0.f, pr8 = 0.f;
        #pragma unroll
        for (int ntl = 0; ntl < 8; ntl++) {
            float t0 = tanh_hw(c[ntl][0]);
            float t1 = tanh_hw(c[ntl][1]);
            float t2 = tanh_hw(c[ntl][2]);
            float t3 = tanh_hw(c[ntl][3]);
            float2 wp = sWP[(ntB + ntl) * 4 + tig];
            pr0 += t0 * wp.x + t1 * wp.y;
            pr8 += t2 * wp.x + t3 * wp.y;
            const int kg = ktOwn + (ntl >> 1), hh = (ntl & 1) << 1;
            a[kg][hh]     = f16x2(t0, t1);
            a[kg][hh + 1] = f16x2(t2, t3);
        }

        // ---- exchange fragment quarters (double-buffered, one barrier) ----
        uint4* xw = sX + (((t & 1) << 1) + wid) * 128;
        #pragma unroll
        for (int g = 0; g < 4; g++)
            xw[g * 32 + lane] = make_uint4(a[ktOwn + g][0], a[ktOwn + g][1],
                                           a[ktOwn + g][2], a[ktOwn + g][3]);
        __syncthreads();
        const uint4* xr = sX + (((t & 1) << 1) + (wid ^ 1)) * 128;
        #pragma unroll
        for (int g = 0; g < 4; g++) {
            uint4 v = xr[g * 32 + lane];
            a[ktOth + g][0] = v.x; a[ktOth + g][1] = v.y;
            a[ktOth + g][2] = v.z; a[ktOth + g][3] = v.w;
        }

        // ---- scalar recursions + x tile (both warps duplicate) ----
        oacc0 = oacc0 * BETA_C + pr0;
        oacc8 = oacc8 * BETA_C + pr8;
        racc0 = racc0 * BETA_C + prev0 * prev0;  prev0 = x0c.x;
        racc8 = racc8 * BETA_C + prev8 * prev8;  prev8 = x8c.x;

        a[8][0] = (tig == 0) ? f16x2(x0n.x, x0n.y) : (tig == 1) ? ONEH : 0u;
        a[8][1] = (tig == 0) ? f16x2(x8n.x, x8n.y) : (tig == 1) ? ONEH : 0u;
        x0c = x0n; x8c = x8n;
    }

    // ---- reduce omega across tig lanes, then across the two n-halves ----
    oacc0 += __shfl_xor_sync(0xffffffffu, oacc0, 1);
    oacc0 += __shfl_xor_sync(0xffffffffu, oacc0, 2);
    oacc8 += __shfl_xor_sync(0xffffffffu, oacc8, 1);
    oacc8 += __shfl_xor_sync(0xffffffffu, oacc8, 2);

    if (wid == 1 && tig == 0) {
        sRed[gid]     = oacc0;
        sRed[gid + 8] = oacc8;
    }
    __syncthreads();
    if (wid == 0 && tig == 0) {
        const float geo = 1.0f / (1.0f - BETA_C);   // beta^512 underflows
        out[bBase + r0] = racc0 * ALPHA_C + (oacc0 + sRed[gid])     + bout * geo;
        out[bBase + r8] = racc8 * ALPHA_C + (oacc8 + sRed[gid + 8]) + bout * geo;
    }
}

extern "C" void kernel_launch(void* const* d_in, const int* in_sizes, int n_in,
                              void* d_out, int out_size) {
    const float* input = (const float*)d_in[0];
    const float* W_rec = (const float*)d_in[1];
    const float* b_rec = (const float*)d_in[2];
    const float* W_out = (const float*)d_in[3];
    const float* b_out = (const float*)d_in[4];
    float* out = (float*)d_out;

    cudaFuncSetAttribute(rnn_kernel, cudaFuncAttributeMaxDynamicSharedMemorySize,
                         SMEM_TOT);
    rnn_kernel<<<B_TOTAL / BM, NTHREADS, SMEM_TOT>>>(input, W_rec, b_rec,
                                                     W_out, b_out, out);
    (void)in_sizes; (void)n_in; (void)out_size;
}